// round 14
// baseline (speedup 1.0000x reference)
#include <cuda_runtime.h>
#include <cuda_fp16.h>
#include <cstdint>
#include <math.h>

#define T_STEPS 1000
#define I_DIM   100
#define H_DIM   5000
#define H4      (H_DIM/4)            // 1250 float4 per fp32 row
#define O_DIM   100
#define ALPHA_F 0.1f
#define NOISE_F 0.1f

#define NBLK   148       // persistent grid: one CTA per SM
#define NTH    512
#define NWARP  (NTH/32)
#define MAXR   34        // max rows per CTA

#define NC        5      // column chunks per step (5000 = 5 * 1000)
#define CHW       1000   // columns per chunk
#define CHW4      250    // float4 of r per chunk
#define CU4       125    // uint4 (8 halves) per row per chunk
#define STAGES    3
#define BLOCK_U4  (MAXR * CU4)                 // 4250 uint4 = 68000 B
#define STAGE_U4  BLOCK_U4
#define DYN_BYTES (STAGES*STAGE_U4*16 + CHW4*16)        // 208000 B

__device__ float g_inj[(size_t)T_STEPS * H_DIM];
__device__ uint4 g_wh4[(size_t)NBLK * NC * BLOCK_U4];   // fp16 W, CTA/chunk-blocked
__device__ int   g_cnt[(size_t)(T_STEPS + 1) * NC];     // per-(t,chunk) ready counters

// ---------------------------------------------------------------------------
// Zero the ready counters (every launch, for graph-replay determinism).
// ---------------------------------------------------------------------------
__global__ void zero_k() {
    const int i = blockIdx.x * blockDim.x + threadIdx.x;
    if (i < (T_STEPS + 1) * NC) g_cnt[i] = 0;
}

// ---------------------------------------------------------------------------
// Convert + reorganize W_rec fp32 -> fp16 into per-(CTA, chunk) contiguous
// blocks of MAXR rows x 1000 cols (row lr at block + lr*2000 B).
// (This layout was validated by the passing R8 run.)
// ---------------------------------------------------------------------------
__global__ void cvt_k(const float* __restrict__ W) {
    const size_t total = (size_t)NBLK * NC * MAXR * CU4;
    const size_t idx = (size_t)blockIdx.x * blockDim.x + threadIdx.x;
    if (idx >= total) return;
    const int    j  = (int)(idx % CU4);
    const size_t r1 = idx / CU4;
    const int    lr = (int)(r1 % MAXR);
    const size_t r2 = r1 / MAXR;
    const int    c  = (int)(r2 % NC);
    const int    b  = (int)(r2 / NC);

    const int row0  = (int)(((long long)b     * H_DIM) / NBLK);
    const int nrows = (int)(((long long)(b+1) * H_DIM) / NBLK) - row0;
    if (lr >= nrows) return;

    const float4* s = reinterpret_cast<const float4*>(W)
                    + (size_t)(row0 + lr) * H4 + c * (CU4 * 2) + 2 * j;
    const float4 a  = __ldcs(s);
    const float4 bb = __ldcs(s + 1);
    uint4 o;
    __half2* p = reinterpret_cast<__half2*>(&o);
    p[0] = __floats2half2_rn(a.x,  a.y);
    p[1] = __floats2half2_rn(a.z,  a.w);
    p[2] = __floats2half2_rn(bb.x, bb.y);
    p[3] = __floats2half2_rn(bb.z, bb.w);
    g_wh4[idx] = o;
}

// ---------------------------------------------------------------------------
// inj[t][h] = sum_i u[t][i] * W_in[h][i] + 0.1 * noise[t][h]
// ---------------------------------------------------------------------------
__global__ void inj_k(const float* __restrict__ u,
                      const float* __restrict__ noise,
                      const float* __restrict__ W_in) {
    __shared__ float u_s[I_DIM];
    const int t   = blockIdx.y;
    const int tid = threadIdx.x;
    if (tid < I_DIM) u_s[tid] = u[(size_t)t * I_DIM + tid];
    __syncthreads();

    const int h = blockIdx.x * blockDim.x + tid;
    if (h < H_DIM) {
        const float4* w4 = reinterpret_cast<const float4*>(W_in + (size_t)h * I_DIM);
        float acc = 0.0f;
#pragma unroll
        for (int i = 0; i < I_DIM / 4; i++) {
            float4 w = __ldg(&w4[i]);
            acc = fmaf(w.x, u_s[4*i+0], acc);
            acc = fmaf(w.y, u_s[4*i+1], acc);
            acc = fmaf(w.z, u_s[4*i+2], acc);
            acc = fmaf(w.w, u_s[4*i+3], acc);
        }
        g_inj[(size_t)t * H_DIM + h] = acc + NOISE_F * noise[(size_t)t * H_DIM + h];
    }
}

// ---------------------------------------------------------------------------
// Persistent scan. W pipeline = proven R7 ring (cp.async, depth 2, rolling
// stage). Grid barrier replaced by per-(t,chunk) ready counters with a
// VOLATILE poll (a non-volatile __ldcg spin is legally deleted by the
// compiler -- the R11/R12 failure mode). r_t is staged coherently into
// smem with __ldcg after the poll + acquire fence.
// ---------------------------------------------------------------------------
__device__ __forceinline__ void cp16(unsigned int daddr, const uint4* src) {
    asm volatile("cp.async.cg.shared.global [%0], [%1], 16;"
                 :: "r"(daddr), "l"(src));
}

__device__ __forceinline__ void fma8(float4& a, const uint4 wv,
                                     const float4 rA, const float4 rB) {
    const __half2* h = reinterpret_cast<const __half2*>(&wv);
    const float2 f0 = __half22float2(h[0]);
    const float2 f1 = __half22float2(h[1]);
    const float2 f2 = __half22float2(h[2]);
    const float2 f3 = __half22float2(h[3]);
    a.x = fmaf(f0.x, rA.x, a.x); a.y = fmaf(f0.y, rA.y, a.y);
    a.z = fmaf(f1.x, rA.z, a.z); a.w = fmaf(f1.y, rA.w, a.w);
    a.x = fmaf(f2.x, rB.x, a.x); a.y = fmaf(f2.y, rB.y, a.y);
    a.z = fmaf(f3.x, rB.z, a.z); a.w = fmaf(f3.y, rB.w, a.w);
}

__global__ void __launch_bounds__(NTH, 1)
scan_k(const float* __restrict__ r_in,
       float* __restrict__ hs) {
    extern __shared__ uint4 dynu[];
    uint4*  wbuf = dynu;                                   // [STAGES][BLOCK_U4]
    float4* r_s4 = reinterpret_cast<float4*>(dynu + STAGES * STAGE_U4);  // 250

    const int tid  = threadIdx.x;
    const int bid  = blockIdx.x;
    const int wid  = tid >> 5;
    const int lane = tid & 31;

    const int row0  = (int)(((long long)bid     * H_DIM) / NBLK);
    const int row1  = (int)(((long long)(bid+1) * H_DIM) / NBLK);
    const int nrows = row1 - row0;                         // 33 or 34

    const int lr0 = wid;
    const int lr1 = wid + NWARP;
    const int lr2 = wid + 2 * NWARP;
    const bool has2 = (lr2 < nrows);

    // Expected arrival count per column chunk (CTAs whose rows intersect it).
    int expect[NC];
#pragma unroll
    for (int c = 0; c < NC; c++) {
        int e = 0;
        for (int b = 0; b < NBLK; b++) {
            const int r0 = (int)(((long long)b     * H_DIM) / NBLK);
            const int r1 = (int)(((long long)(b+1) * H_DIM) / NBLK);
            if (r0 < (c + 1) * CHW && r1 > c * CHW) e++;
        }
        expect[c] = e;
    }
    const int c_lo = row0 / CHW;
    const int c_hi = (row1 - 1) / CHW;

    // hidden_states[0] = r_in; lane-0 registers hold the membrane state x.
    if (tid < nrows) hs[row0 + tid] = r_in[row0 + tid];
    float x0 = 0.f, x1 = 0.f, x2 = 0.f;
    if (lane == 0) {
        x0 = atanhf(__ldg(r_in + row0 + lr0));
        x1 = atanhf(__ldg(r_in + row0 + lr1));
        if (has2) x2 = atanhf(__ldg(r_in + row0 + lr2));
    }
    __syncthreads();

    const uint4* gbase = g_wh4 + (size_t)bid * NC * BLOCK_U4;
    const int nldg = nrows * CU4;

    // Issue data chunk c into smem stage s (pre-blocked -> fully coalesced).
    auto issue = [&](int c, int s) {
        const uint4* src = gbase + (size_t)c * BLOCK_U4;
        uint4* dst = wbuf + s * STAGE_U4;
        for (int i = tid; i < nldg; i += NTH)
            cp16((unsigned int)__cvta_generic_to_shared(dst + i), src + i);
        asm volatile("cp.async.commit_group;" ::: "memory");
    };

    issue(0, 0); issue(1, 1);                              // prologue: k=0,1
    int stage = 0;                                         // k % 3 (rolls over steps)
    int nstage = 2, nchunk = 2;                            // slot/data of chunk k+2

    for (int t = 0; t < T_STEPS; t++) {
        const float4* rbase = (t == 0)
            ? reinterpret_cast<const float4*>(r_in)
            : reinterpret_cast<const float4*>(hs + (size_t)t * H_DIM);

        float4 a0 = make_float4(0.f,0.f,0.f,0.f);
        float4 a1 = make_float4(0.f,0.f,0.f,0.f);
        float4 a2 = make_float4(0.f,0.f,0.f,0.f);

        for (int c = 0; c < NC; c++) {
            asm volatile("cp.async.wait_group 1;" ::: "memory");
            __syncthreads();               // W chunk k resident; stage k-1 free;
                                           // previous chunk's r_s readers done
            issue(nchunk, nstage);         // refill freed stage (W of chunk k+2)
            nstage = (nstage == 2) ? 0 : nstage + 1;
            nchunk = (nchunk == NC - 1) ? 0 : nchunk + 1;

            const uint4* wb = wbuf + stage * STAGE_U4;
            stage = (stage == 2) ? 0 : stage + 1;

            // Wait for producers of r_t columns [1000c, 1000c+1000).
            // VOLATILE poll: a plain __ldcg spin is a side-effect-free loop
            // the compiler may remove.
            if (t > 0) {
                const volatile int* cp =
                    (const volatile int*)&g_cnt[t * NC + c];
                const int exp_c = expect[c];
                while (*cp < exp_c) { }
                __threadfence();           // acquire: order r reads after poll
            }
            // Stage the r chunk coherently (L2 path) into smem.
            if (tid < CHW4) r_s4[tid] = __ldcg(rbase + c * CHW4 + tid);
            __syncthreads();               // r_s visible to all warps

            const uint4* w0 = wb + lr0 * CU4;
            const uint4* w1 = wb + lr1 * CU4;
            const uint4* w2 = wb + lr2 * CU4;

#pragma unroll
            for (int it = 0; it < 4; it++) {
                const int col = lane + it * 32;
                if (it < 3 || lane < CU4 - 96) {
                    const float4 rA = r_s4[2*col];
                    const float4 rB = r_s4[2*col + 1];
                    fma8(a0, w0[col], rA, rB);
                    fma8(a1, w1[col], rA, rB);
                    if (has2) fma8(a2, w2[col], rA, rB);
                }
            }
        }

        // Reduce + state update for the warp's rows.
        float s0 = (a0.x + a0.y) + (a0.z + a0.w);
        float s1 = (a1.x + a1.y) + (a1.z + a1.w);
        float s2 = (a2.x + a2.y) + (a2.z + a2.w);
#pragma unroll
        for (int sh = 16; sh; sh >>= 1) {
            s0 += __shfl_down_sync(0xffffffffu, s0, sh);
            s1 += __shfl_down_sync(0xffffffffu, s1, sh);
            s2 += __shfl_down_sync(0xffffffffu, s2, sh);
        }
        if (lane == 0) {
            {   const int row = row0 + lr0;
                x0 = (1.0f-ALPHA_F)*x0
                   + ALPHA_F*(s0 + __ldcg(&g_inj[(size_t)t*H_DIM + row]));
                hs[(size_t)(t+1)*H_DIM + row] = tanhf(x0); }
            {   const int row = row0 + lr1;
                x1 = (1.0f-ALPHA_F)*x1
                   + ALPHA_F*(s1 + __ldcg(&g_inj[(size_t)t*H_DIM + row]));
                hs[(size_t)(t+1)*H_DIM + row] = tanhf(x1); }
            if (has2) {
                const int row = row0 + lr2;
                x2 = (1.0f-ALPHA_F)*x2
                   + ALPHA_F*(s2 + __ldcg(&g_inj[(size_t)t*H_DIM + row]));
                hs[(size_t)(t+1)*H_DIM + row] = tanhf(x2); }
            __threadfence();               // release this warp's stores
        }
        __syncthreads();                   // all CTA rows stored + fenced

        if (tid == 0) {                    // announce r_{t+1} rows ready
            for (int c = c_lo; c <= c_hi; c++)
                atomicAdd(&g_cnt[(t + 1) * NC + c], 1);
        }
    }
    asm volatile("cp.async.wait_group 0;" ::: "memory");
    __syncthreads();
}

// ---------------------------------------------------------------------------
// o[t][j] = sum_h hs[t+1][h] * W_out[j][h]
// ---------------------------------------------------------------------------
__global__ void out_k(const float* __restrict__ hs,
                      const float* __restrict__ W_out,
                      float* __restrict__ o) {
    __shared__ float r_s[H_DIM];
    const int t    = blockIdx.x;
    const int tid  = threadIdx.x;
    const int wid  = tid >> 5;
    const int lane = tid & 31;

    const float* r = hs + (size_t)(t + 1) * H_DIM;
    for (int c = tid; c < H_DIM; c += blockDim.x) r_s[c] = r[c];
    __syncthreads();

    for (int j = wid; j < O_DIM; j += blockDim.x / 32) {
        const float* wrow = W_out + (size_t)j * H_DIM;
        float acc = 0.0f;
        for (int c = lane; c < H_DIM; c += 32)
            acc = fmaf(__ldg(wrow + c), r_s[c], acc);
#pragma unroll
        for (int s = 16; s; s >>= 1) acc += __shfl_down_sync(0xffffffffu, acc, s);
        if (lane == 0) o[(size_t)t * O_DIM + j] = acc;
    }
}

// ---------------------------------------------------------------------------
// Inputs: u (T,I), r (H), noise (T,H), W_in (H,I), W_rec (H,H), W_out (O,H).
// Output: hidden_states (T+1,H) then o (T,O), fp32.
// ---------------------------------------------------------------------------
extern "C" void kernel_launch(void* const* d_in, const int* in_sizes, int n_in,
                              void* d_out, int out_size) {
    const float* u     = (const float*)d_in[0];
    const float* r     = (const float*)d_in[1];
    const float* noise = (const float*)d_in[2];
    const float* W_in  = (const float*)d_in[3];
    const float* W_rec = (const float*)d_in[4];
    const float* W_out = (const float*)d_in[5];

    float* hs = (float*)d_out;                       // (T+1, H)
    float* o  = hs + (size_t)(T_STEPS + 1) * H_DIM;  // (T, O)

    cudaFuncSetAttribute(scan_k, cudaFuncAttributeMaxDynamicSharedMemorySize,
                         DYN_BYTES);

    zero_k<<<((T_STEPS + 1) * NC + 255) / 256, 256>>>();
    dim3 gi((H_DIM + 255) / 256, T_STEPS);
    inj_k<<<gi, 256>>>(u, noise, W_in);
    const size_t cvt_total = (size_t)NBLK * NC * MAXR * CU4;
    cvt_k<<<(int)((cvt_total + 255) / 256), 256>>>(W_rec);
    scan_k<<<NBLK, NTH, DYN_BYTES>>>(r, hs);
    out_k<<<T_STEPS, 256>>>(hs, W_out, o);
}

// round 15
// speedup vs baseline: 1.3157x; 1.3157x over previous
#include <cuda_runtime.h>
#include <cuda_fp16.h>
#include <cstdint>
#include <math.h>

#define T_STEPS 1000
#define I_DIM   100
#define H_DIM   5000
#define H4      (H_DIM/4)            // 1250 float4 per fp32 row
#define O_DIM   100
#define ALPHA_F 0.1f
#define NOISE_F 0.1f

#define NBLK   148       // persistent grid: one CTA per SM
#define NTH    512
#define NWARP  (NTH/32)
#define MAXR   34        // max rows per CTA

#define NC        5      // column chunks per step (5000 = 5 * 1000)
#define CHW4      250    // float4 of r per chunk
#define CU4       125    // uint4 (8 halves) per row per chunk
#define STAGES    3
#define BLOCK_U4  (MAXR * CU4)                 // 4250 uint4 = 68000 B
#define STAGE_U4  BLOCK_U4
#define DYN_BYTES (STAGES*STAGE_U4*16)         // 204000 B

__device__ float    g_inj[(size_t)T_STEPS * H_DIM];
__device__ uint4    g_wh4[(size_t)NBLK * NC * BLOCK_U4];  // fp16 W, CTA/chunk-blocked
__device__ unsigned g_bar;

__global__ void reset_k() { g_bar = 0u; }

// ---------------------------------------------------------------------------
// Convert + reorganize W_rec fp32 -> fp16 into per-(CTA, chunk) contiguous
// blocks of MAXR rows x 1000 cols (validated by the R14 passing run).
// ---------------------------------------------------------------------------
__global__ void cvt_k(const float* __restrict__ W) {
    const size_t total = (size_t)NBLK * NC * MAXR * CU4;
    const size_t idx = (size_t)blockIdx.x * blockDim.x + threadIdx.x;
    if (idx >= total) return;
    const int    j  = (int)(idx % CU4);
    const size_t r1 = idx / CU4;
    const int    lr = (int)(r1 % MAXR);
    const size_t r2 = r1 / MAXR;
    const int    c  = (int)(r2 % NC);
    const int    b  = (int)(r2 / NC);

    const int row0  = (int)(((long long)b     * H_DIM) / NBLK);
    const int nrows = (int)(((long long)(b+1) * H_DIM) / NBLK) - row0;
    if (lr >= nrows) return;

    const float4* s = reinterpret_cast<const float4*>(W)
                    + (size_t)(row0 + lr) * H4 + c * (CU4 * 2) + 2 * j;
    const float4 a  = __ldcs(s);
    const float4 bb = __ldcs(s + 1);
    uint4 o;
    __half2* p = reinterpret_cast<__half2*>(&o);
    p[0] = __floats2half2_rn(a.x,  a.y);
    p[1] = __floats2half2_rn(a.z,  a.w);
    p[2] = __floats2half2_rn(bb.x, bb.y);
    p[3] = __floats2half2_rn(bb.z, bb.w);
    g_wh4[idx] = o;
}

// ---------------------------------------------------------------------------
// inj[t][h] = sum_i u[t][i] * W_in[h][i] + 0.1 * noise[t][h]
// ---------------------------------------------------------------------------
__global__ void inj_k(const float* __restrict__ u,
                      const float* __restrict__ noise,
                      const float* __restrict__ W_in) {
    __shared__ float u_s[I_DIM];
    const int t   = blockIdx.y;
    const int tid = threadIdx.x;
    if (tid < I_DIM) u_s[tid] = u[(size_t)t * I_DIM + tid];
    __syncthreads();

    const int h = blockIdx.x * blockDim.x + tid;
    if (h < H_DIM) {
        const float4* w4 = reinterpret_cast<const float4*>(W_in + (size_t)h * I_DIM);
        float acc = 0.0f;
#pragma unroll
        for (int i = 0; i < I_DIM / 4; i++) {
            float4 w = __ldg(&w4[i]);
            acc = fmaf(w.x, u_s[4*i+0], acc);
            acc = fmaf(w.y, u_s[4*i+1], acc);
            acc = fmaf(w.z, u_s[4*i+2], acc);
            acc = fmaf(w.w, u_s[4*i+3], acc);
        }
        g_inj[(size_t)t * H_DIM + h] = acc + NOISE_F * noise[(size_t)t * H_DIM + h];
    }
}

// ---------------------------------------------------------------------------
// Persistent scan (R7 skeleton). W: cp.async depth-2 ring, blocked layout,
// one __syncthreads per chunk. r: per-warp direct __ldca reads (L1-cached;
// hs[t] lines are first-touched in step t, so L1 can never be stale).
// inj: prefetched into lane-0 registers at step top. Grid barrier with
// volatile poll (tid 0 only) per step.
// ---------------------------------------------------------------------------
__device__ __forceinline__ void cp16(unsigned int daddr, const uint4* src) {
    asm volatile("cp.async.cg.shared.global [%0], [%1], 16;"
                 :: "r"(daddr), "l"(src));
}

__device__ __forceinline__ void fma8(float4& a, const uint4 wv,
                                     const float4 rA, const float4 rB) {
    const __half2* h = reinterpret_cast<const __half2*>(&wv);
    const float2 f0 = __half22float2(h[0]);
    const float2 f1 = __half22float2(h[1]);
    const float2 f2 = __half22float2(h[2]);
    const float2 f3 = __half22float2(h[3]);
    a.x = fmaf(f0.x, rA.x, a.x); a.y = fmaf(f0.y, rA.y, a.y);
    a.z = fmaf(f1.x, rA.z, a.z); a.w = fmaf(f1.y, rA.w, a.w);
    a.x = fmaf(f2.x, rB.x, a.x); a.y = fmaf(f2.y, rB.y, a.y);
    a.z = fmaf(f3.x, rB.z, a.z); a.w = fmaf(f3.y, rB.w, a.w);
}

__global__ void __launch_bounds__(NTH, 1)
scan_k(const float* __restrict__ r_in,
       float* __restrict__ hs) {
    extern __shared__ uint4 dynu[];
    uint4* wbuf = dynu;                                    // [STAGES][BLOCK_U4]

    const int tid  = threadIdx.x;
    const int bid  = blockIdx.x;
    const int wid  = tid >> 5;
    const int lane = tid & 31;

    const int row0  = (int)(((long long)bid     * H_DIM) / NBLK);
    const int row1  = (int)(((long long)(bid+1) * H_DIM) / NBLK);
    const int nrows = row1 - row0;                         // 33 or 34

    const int lr0 = wid;
    const int lr1 = wid + NWARP;
    const int lr2 = wid + 2 * NWARP;
    const bool has2 = (lr2 < nrows);

    // hidden_states[0] = r_in; membrane state x in lane-0 registers.
    if (tid < nrows) hs[row0 + tid] = r_in[row0 + tid];
    float x0 = 0.f, x1 = 0.f, x2 = 0.f;
    if (lane == 0) {
        x0 = atanhf(__ldg(r_in + row0 + lr0));
        x1 = atanhf(__ldg(r_in + row0 + lr1));
        if (has2) x2 = atanhf(__ldg(r_in + row0 + lr2));
    }
    __syncthreads();

    const uint4* gbase = g_wh4 + (size_t)bid * NC * BLOCK_U4;
    const int nldg = nrows * CU4;

    // Issue data chunk c into smem stage s (blocked -> fully coalesced).
    auto issue = [&](int c, int s) {
        const uint4* src = gbase + (size_t)c * BLOCK_U4;
        uint4* dst = wbuf + s * STAGE_U4;
        for (int i = tid; i < nldg; i += NTH)
            cp16((unsigned int)__cvta_generic_to_shared(dst + i), src + i);
        asm volatile("cp.async.commit_group;" ::: "memory");
    };

    issue(0, 0); issue(1, 1);                              // prologue: k=0,1
    int stage = 0;                                         // k % 3, rolls over steps
    int nstage = 2, nchunk = 2;                            // slot/data of chunk k+2

    for (int t = 0; t < T_STEPS; t++) {
        const float4* rbase = (t == 0)
            ? reinterpret_cast<const float4*>(r_in)
            : reinterpret_cast<const float4*>(hs + (size_t)t * H_DIM);

        // Prefetch injection early (consumed in the step tail).
        float inj0 = 0.f, inj1 = 0.f, inj2 = 0.f;
        if (lane == 0) {
            inj0 = __ldcg(&g_inj[(size_t)t * H_DIM + row0 + lr0]);
            inj1 = __ldcg(&g_inj[(size_t)t * H_DIM + row0 + lr1]);
            if (has2) inj2 = __ldcg(&g_inj[(size_t)t * H_DIM + row0 + lr2]);
        }

        float4 a0 = make_float4(0.f,0.f,0.f,0.f);
        float4 a1 = make_float4(0.f,0.f,0.f,0.f);
        float4 a2 = make_float4(0.f,0.f,0.f,0.f);

        for (int c = 0; c < NC; c++) {
            asm volatile("cp.async.wait_group 1;" ::: "memory");
            __syncthreads();               // W chunk k resident; stage k-1 free

            issue(nchunk, nstage);         // refill freed stage (chunk k+2)
            nstage = (nstage == 2) ? 0 : nstage + 1;
            nchunk = (nchunk == NC - 1) ? 0 : nchunk + 1;

            const uint4* wb = wbuf + stage * STAGE_U4;
            stage = (stage == 2) ? 0 : stage + 1;

            const float4* rc = rbase + c * CHW4;
            const uint4* w0 = wb + lr0 * CU4;
            const uint4* w1 = wb + lr1 * CU4;
            const uint4* w2 = wb + lr2 * CU4;

#pragma unroll
            for (int it = 0; it < 4; it++) {
                const int col = lane + it * 32;
                if (it < 3 || lane < CU4 - 96) {
                    const float4 rA = __ldca(rc + 2*col);      // L1 path
                    const float4 rB = __ldca(rc + 2*col + 1);
                    fma8(a0, w0[col], rA, rB);
                    fma8(a1, w1[col], rA, rB);
                    if (has2) fma8(a2, w2[col], rA, rB);
                }
            }
        }

        // Reduce + state update for the warp's rows.
        float s0 = (a0.x + a0.y) + (a0.z + a0.w);
        float s1 = (a1.x + a1.y) + (a1.z + a1.w);
        float s2 = (a2.x + a2.y) + (a2.z + a2.w);
#pragma unroll
        for (int sh = 16; sh; sh >>= 1) {
            s0 += __shfl_down_sync(0xffffffffu, s0, sh);
            s1 += __shfl_down_sync(0xffffffffu, s1, sh);
            s2 += __shfl_down_sync(0xffffffffu, s2, sh);
        }
        if (lane == 0) {
            {   const int row = row0 + lr0;
                x0 = (1.0f-ALPHA_F)*x0 + ALPHA_F*(s0 + inj0);
                hs[(size_t)(t+1)*H_DIM + row] = tanhf(x0); }
            {   const int row = row0 + lr1;
                x1 = (1.0f-ALPHA_F)*x1 + ALPHA_F*(s1 + inj1);
                hs[(size_t)(t+1)*H_DIM + row] = tanhf(x1); }
            if (has2) {
                const int row = row0 + lr2;
                x2 = (1.0f-ALPHA_F)*x2 + ALPHA_F*(s2 + inj2);
                hs[(size_t)(t+1)*H_DIM + row] = tanhf(x2); }
            __threadfence();               // release this warp's stores
        }
        __syncthreads();                   // all CTA rows stored + fenced

        // Grid barrier: atomic arrive (tid 0) + volatile read-only poll.
        if (tid == 0) {
            atomicAdd(&g_bar, 1u);
            const unsigned target = (unsigned)(t + 1) * (unsigned)NBLK;
            while (*((volatile unsigned*)&g_bar) < target) { }
            __threadfence();               // acquire
        }
        __syncthreads();
    }
    asm volatile("cp.async.wait_group 0;" ::: "memory");
    __syncthreads();
}

// ---------------------------------------------------------------------------
// o[t][j] = sum_h hs[t+1][h] * W_out[j][h]
// ---------------------------------------------------------------------------
__global__ void out_k(const float* __restrict__ hs,
                      const float* __restrict__ W_out,
                      float* __restrict__ o) {
    __shared__ float r_s[H_DIM];
    const int t    = blockIdx.x;
    const int tid  = threadIdx.x;
    const int wid  = tid >> 5;
    const int lane = tid & 31;

    const float* r = hs + (size_t)(t + 1) * H_DIM;
    for (int c = tid; c < H_DIM; c += blockDim.x) r_s[c] = r[c];
    __syncthreads();

    for (int j = wid; j < O_DIM; j += blockDim.x / 32) {
        const float* wrow = W_out + (size_t)j * H_DIM;
        float acc = 0.0f;
        for (int c = lane; c < H_DIM; c += 32)
            acc = fmaf(__ldg(wrow + c), r_s[c], acc);
#pragma unroll
        for (int s = 16; s; s >>= 1) acc += __shfl_down_sync(0xffffffffu, acc, s);
        if (lane == 0) o[(size_t)t * O_DIM + j] = acc;
    }
}

// ---------------------------------------------------------------------------
// Inputs: u (T,I), r (H), noise (T,H), W_in (H,I), W_rec (H,H), W_out (O,H).
// Output: hidden_states (T+1,H) then o (T,O), fp32.
// ---------------------------------------------------------------------------
extern "C" void kernel_launch(void* const* d_in, const int* in_sizes, int n_in,
                              void* d_out, int out_size) {
    const float* u     = (const float*)d_in[0];
    const float* r     = (const float*)d_in[1];
    const float* noise = (const float*)d_in[2];
    const float* W_in  = (const float*)d_in[3];
    const float* W_rec = (const float*)d_in[4];
    const float* W_out = (const float*)d_in[5];

    float* hs = (float*)d_out;                       // (T+1, H)
    float* o  = hs + (size_t)(T_STEPS + 1) * H_DIM;  // (T, O)

    cudaFuncSetAttribute(scan_k, cudaFuncAttributeMaxDynamicSharedMemorySize,
                         DYN_BYTES);

    reset_k<<<1, 1>>>();
    dim3 gi((H_DIM + 255) / 256, T_STEPS);
    inj_k<<<gi, 256>>>(u, noise, W_in);
    const size_t cvt_total = (size_t)NBLK * NC * MAXR * CU4;
    cvt_k<<<(int)((cvt_total + 255) / 256), 256>>>(W_rec);
    scan_k<<<NBLK, NTH, DYN_BYTES>>>(r, hs);
    out_k<<<T_STEPS, 256>>>(hs, W_out, o);
}